// round 10
// baseline (speedup 1.0000x reference)
#include <cuda_runtime.h>
#include <cuda_fp16.h>

typedef unsigned long long u64;
typedef unsigned int u32;
#define BATCH 131072

// inter-phase state: concat layout [b][96], enc at 0..63, cent at 64..95
__device__ float g_h0[(size_t)BATCH * 96];
__device__ float g_c0[(size_t)BATCH * 96];

__device__ __forceinline__ float ex2f(float x){ float y; asm("ex2.approx.f32 %0, %1;" : "=f"(y) : "f"(x)); return y; }
__device__ __forceinline__ float rcpf(float x){ float y; asm("rcp.approx.f32 %0, %1;" : "=f"(y) : "f"(x)); return y; }
__device__ __forceinline__ float sigmf(float x){ return rcpf(1.0f + ex2f(-1.4426950408889634f * x)); }
__device__ __forceinline__ float tanhf_(float x){ return 1.0f - 2.0f * rcpf(1.0f + ex2f(2.8853900817779268f * x)); }

__device__ __forceinline__ void ffma2(u64 &d, u64 a, u64 b){
    asm("fma.rn.f32x2 %0, %1, %2, %0;" : "+l"(d) : "l"(a), "l"(b));
}
__device__ __forceinline__ float red2(u64 a){
    float lo, hi; asm("mov.b64 {%0, %1}, %2;" : "=f"(lo), "=f"(hi) : "l"(a)); return lo + hi;
}
__device__ __forceinline__ u32 smem_u32(const void* p){
    u32 a; asm("{ .reg .u64 t; cvta.to.shared.u64 t, %1; cvt.u32.u64 %0, t; }" : "=r"(a) : "l"(p)); return a;
}
__device__ __forceinline__ void ldsm4(u32 &r0, u32 &r1, u32 &r2, u32 &r3, u32 addr){
    asm volatile("ldmatrix.sync.aligned.m8n8.x4.shared.b16 {%0,%1,%2,%3}, [%4];"
        : "=r"(r0), "=r"(r1), "=r"(r2), "=r"(r3) : "r"(addr));
}
__device__ __forceinline__ void mma_f16(float &d0, float &d1, float &d2, float &d3,
                                        const u32* a, u32 b0, u32 b1){
    asm volatile("mma.sync.aligned.m16n8k16.row.col.f32.f16.f16.f32 "
        "{%0,%1,%2,%3}, {%4,%5,%6,%7}, {%8,%9}, {%0,%1,%2,%3};"
        : "+f"(d0), "+f"(d1), "+f"(d2), "+f"(d3)
        : "r"(a[0]), "r"(a[1]), "r"(a[2]), "r"(a[3]), "r"(b0), "r"(b1));
}

// ---------------------------------------------------------------------------
// cent / enc recurrent phase on HMMA, 3-pass (W split hi/lo fp16 -> exact to
// ~2^-22). 32 elems/CTA, 512 thr = 16 warps: rg = wid>>3 (2 x 16 elems),
// cg = wid&7 (8 x H/2 gate-cols). W gate-interleaved: col r = 4j+g.
// x-projection (2 inputs) + bias applied in fp32 in the epilogue.
// ---------------------------------------------------------------------------
template<int H, int T, int OFF>
__global__ __launch_bounds__(512, 1)
void lstm_rec_mma(const float* __restrict__ x_g,
                  const float* __restrict__ Wih, const float* __restrict__ Whh,
                  const float* __restrict__ bih, const float* __restrict__ bhh)
{
    constexpr int G     = 4 * H;
    constexpr int KP    = H + 8;        // halves per row (16B-aligned stride)
    constexpr int WROWB = 2 * KP;       // bytes per row
    constexpr int KC    = H / 16;       // k16 chunks
    constexpr int NPAIR = H / 32;       // n8-tile pairs per warp
    constexpr int NCELL = H / 16;       // n0 cells per warp (=2*NPAIR)
    // SMEM byte offsets
    constexpr int SWHI = 0;
    constexpr int SWLO = SWHI + G * KP * 2;
    constexpr int SHHI = SWLO + G * KP * 2;
    constexpr int SHLO = SHHI + 32 * KP * 2;
    constexpr int SBSD = SHLO + 32 * KP * 2;
    constexpr int SWX0 = SBSD + G * 4;
    constexpr int SWX1 = SWX0 + G * 4;

    extern __shared__ char smc[];
    float* bsd = (float*)(smc + SBSD);
    float* wx0 = (float*)(smc + SWX0);
    float* wx1 = (float*)(smc + SWX1);
    const u32 smb = smem_u32(smc);

    const int tid = threadIdx.x;
    const size_t b0 = (size_t)blockIdx.x * 32;

    // ---- W fill: torch row = g*H+j -> interleaved col r = 4j+g, fp16 hi/lo ----
    for (int i = tid; i < G * H; i += 512){
        int trow = i / H, k = i % H;
        int g = trow / H, j = trow % H;
        float w = Whh[i];
        __half hi = __float2half_rn(w);
        __half lo = __float2half_rn(w - __half2float(hi));
        int r = 4 * j + g;
        *(__half*)(smc + SWHI + (r * KP + k) * 2) = hi;
        *(__half*)(smc + SWLO + (r * KP + k) * 2) = lo;
    }
    for (int i = tid; i < G; i += 512){
        int g = i / H, j = i % H;
        int r = 4 * j + g;
        bsd[r] = bih[i] + bhh[i];
        wx0[r] = Wih[2 * i];
        wx1[r] = Wih[2 * i + 1];
    }
    // h0 = 0
    for (int i = tid; i < 32 * KP; i += 512){
        *(__half*)(smc + SHHI + i * 2) = __float2half_rn(0.f);
        *(__half*)(smc + SHLO + i * 2) = __float2half_rn(0.f);
    }

    const int wid = tid >> 5, lane = tid & 31;
    const int cg = wid & 7, rg = wid >> 3;
    const int e0 = rg * 16, colbase = cg * (H / 2);
    const int tg = lane & 3, gq = lane >> 2;
    const bool is_even = (tg & 1) == 0;

    // ldmatrix per-lane addresses
    const int a_row = e0 + (lane & 7) + ((lane >> 3) & 1) * 8;
    const u32 a_koff = ((lane >> 4) & 1) * 16;
    const u32 ah_base = smb + SHHI + (u32)a_row * WROWB + a_koff;
    const u32 al_base = smb + SHLO + (u32)a_row * WROWB + a_koff;
    const int b4_row = colbase + ((lane >> 4) << 3) + (lane & 7);
    const u32 b4_koff = ((lane >> 3) & 1) * 16;
    const u32 bh4_base = smb + SWHI + (u32)b4_row * WROWB + b4_koff;
    const u32 bl4_base = smb + SWLO + (u32)b4_row * WROWB + b4_koff;

    const int eA = e0 + gq, eB = eA + 8;
    float cA[NCELL], cB[NCELL];
    #pragma unroll
    for (int n0 = 0; n0 < NCELL; n0++){ cA[n0] = 0.f; cB[n0] = 0.f; }

    __syncthreads();

    for (int t = 0; t < T; t++){
        // x inputs for this step (even lanes consume; L1-resident after step 1)
        float2 xA = *(const float2*)(x_g + (b0 + eA) * (size_t)(2 * T) + 2 * t);
        float2 xB = *(const float2*)(x_g + (b0 + eB) * (size_t)(2 * T) + 2 * t);

        // A fragments (h hi/lo)
        u32 ahi[KC][4], alo[KC][4];
        #pragma unroll
        for (int kc = 0; kc < KC; kc++){
            ldsm4(ahi[kc][0], ahi[kc][1], ahi[kc][2], ahi[kc][3], ah_base + kc * 32);
            ldsm4(alo[kc][0], alo[kc][1], alo[kc][2], alo[kc][3], al_base + kc * 32);
        }
        __syncthreads();   // A consumed -> h SMEM writable

        #pragma unroll
        for (int p = 0; p < NPAIR; p++){
            float d[2][4];
            #pragma unroll
            for (int h2 = 0; h2 < 2; h2++)
                #pragma unroll
                for (int r2 = 0; r2 < 4; r2++) d[h2][r2] = 0.f;
            const u32 bhp = bh4_base + (u32)(p * 16) * WROWB;
            const u32 blp = bl4_base + (u32)(p * 16) * WROWB;
            #pragma unroll
            for (int kc = 0; kc < KC; kc++){
                u32 h0q, h1q, h2q, h3q, l0q, l1q, l2q, l3q;
                ldsm4(h0q, h1q, h2q, h3q, bhp + kc * 32);
                ldsm4(l0q, l1q, l2q, l3q, blp + kc * 32);
                mma_f16(d[0][0], d[0][1], d[0][2], d[0][3], ahi[kc], h0q, h1q);
                mma_f16(d[0][0], d[0][1], d[0][2], d[0][3], alo[kc], h0q, h1q);
                mma_f16(d[0][0], d[0][1], d[0][2], d[0][3], ahi[kc], l0q, l1q);
                mma_f16(d[1][0], d[1][1], d[1][2], d[1][3], ahi[kc], h2q, h3q);
                mma_f16(d[1][0], d[1][1], d[1][2], d[1][3], alo[kc], h2q, h3q);
                mma_f16(d[1][0], d[1][1], d[1][2], d[1][3], ahi[kc], l2q, l3q);
            }
            #pragma unroll
            for (int h2 = 0; h2 < 2; h2++){
                const int n0 = 2 * p + h2;
                float d0 = d[h2][0], d1 = d[h2][1], d2 = d[h2][2], d3 = d[h2][3];
                // even lanes hold (i,f); receive (g,o) from lane^1
                float s0 = __shfl_xor_sync(0xffffffffu, d0, 1);
                float s1 = __shfl_xor_sync(0xffffffffu, d1, 1);
                float s2 = __shfl_xor_sync(0xffffffffu, d2, 1);
                float s3 = __shfl_xor_sync(0xffffffffu, d3, 1);
                if (is_even){
                    const int r = colbase + n0 * 8 + 2 * tg;   // = 4j
                    const int j = r >> 2;
                    float bi = bsd[r],   wi0 = wx0[r],   wi1 = wx1[r];
                    float bf = bsd[r+1], wf0 = wx0[r+1], wf1 = wx1[r+1];
                    float bg = bsd[r+2], wg0 = wx0[r+2], wg1 = wx1[r+2];
                    float bo = bsd[r+3], wo0 = wx0[r+3], wo1 = wx1[r+3];
                    float giA = d0 + bi + xA.x * wi0 + xA.y * wi1;
                    float gfA = d1 + bf + xA.x * wf0 + xA.y * wf1;
                    float ggA = s0 + bg + xA.x * wg0 + xA.y * wg1;
                    float goA = s1 + bo + xA.x * wo0 + xA.y * wo1;
                    float cnA = sigmf(gfA) * cA[n0] + sigmf(giA) * tanhf_(ggA);
                    float hA  = sigmf(goA) * tanhf_(cnA);
                    float giB = d2 + bi + xB.x * wi0 + xB.y * wi1;
                    float gfB = d3 + bf + xB.x * wf0 + xB.y * wf1;
                    float ggB = s2 + bg + xB.x * wg0 + xB.y * wg1;
                    float goB = s3 + bo + xB.x * wo0 + xB.y * wo1;
                    float cnB = sigmf(gfB) * cB[n0] + sigmf(giB) * tanhf_(ggB);
                    float hB  = sigmf(goB) * tanhf_(cnB);
                    cA[n0] = cnA; cB[n0] = cnB;
                    __half hAh = __float2half_rn(hA);
                    __half hBh = __float2half_rn(hB);
                    *(__half*)(smc + SHHI + (eA * KP + j) * 2) = hAh;
                    *(__half*)(smc + SHHI + (eB * KP + j) * 2) = hBh;
                    *(__half*)(smc + SHLO + (eA * KP + j) * 2) = __float2half_rn(hA - __half2float(hAh));
                    *(__half*)(smc + SHLO + (eB * KP + j) * 2) = __float2half_rn(hB - __half2float(hBh));
                    if (t == T - 1){
                        g_h0[(b0 + eA) * 96 + OFF + j] = hA;
                        g_h0[(b0 + eB) * 96 + OFF + j] = hB;
                        g_c0[(b0 + eA) * 96 + OFF + j] = cnA;
                        g_c0[(b0 + eB) * 96 + OFF + j] = cnB;
                    }
                }
            }
        }
        __syncthreads();   // h ready for next step
    }
}

// ---------------------------------------------------------------------------
// decoder on HMMA, fp16 2-pass (unchanged from round 9 — passing, 2.7e-4)
// ---------------------------------------------------------------------------
#define DNT 512
#define SW_HI   0          // W_hi  [384][104] fp16  (79,872)
#define SH_HI   79872      // h_hi  [32][104]  fp16  (6,656)
#define SH_LO   86528      // h_lo  [32][104]  fp16  (6,656)
#define SH_F32  93184      // h_f32 [32][100]  f32   (12,800)
#define S_BSD   105984     // bias  [384]      f32   (1,536)
#define S_WEX   107520     // [96] f32
#define S_WEY   107904     // [96] f32
#define SM_TOT  108288
#define WROW    208
#define HF32P   100

__global__ __launch_bounds__(DNT, 1)
void lstm_dec_mma(const float* __restrict__ Wih, const float* __restrict__ Whh,
                  const float* __restrict__ bih, const float* __restrict__ bhh,
                  const float* __restrict__ Wemb, const float* __restrict__ bemb,
                  float* __restrict__ out)
{
    extern __shared__ char smc[];
    float* hf32 = (float*)(smc + SH_F32);
    float* bsd  = (float*)(smc + S_BSD);
    float* wex  = (float*)(smc + S_WEX);
    float* wey  = (float*)(smc + S_WEY);
    const u32 smb = smem_u32(smc);

    const int tid = threadIdx.x;
    const size_t b0 = (size_t)blockIdx.x * 32;

    for (int i = tid; i < 384 * 96; i += DNT){
        int trow = i / 96, k = i % 96;
        int g = trow / 96, j = trow % 96;
        float w = Wih[i] + Whh[i];
        int r = 4 * j + g;
        *(__half*)(smc + SW_HI + (r * 104 + k) * 2) = __float2half_rn(w);
    }
    for (int i = tid; i < 384; i += DNT){
        int g = i / 96, j = i % 96;
        bsd[4 * j + g] = bih[i] + bhh[i];
    }
    for (int i = tid; i < 96; i += DNT){ wex[i] = Wemb[i]; wey[i] = Wemb[96 + i]; }

    for (int i = tid; i < 32 * 96; i += DNT){
        int e = i / 96, j = i % 96;
        float v = g_h0[(b0 + e) * 96 + j];
        __half hi = __float2half_rn(v);
        __half lo = __float2half_rn(v - __half2float(hi));
        hf32[e * HF32P + j] = v;
        *(__half*)(smc + SH_HI + (e * 104 + j) * 2) = hi;
        *(__half*)(smc + SH_LO + (e * 104 + j) * 2) = lo;
    }

    const int wid = tid >> 5, lane = tid & 31;
    const int cg = wid & 7, rg = wid >> 3;
    const int e0 = rg * 16, colbase = cg * 48;
    const int tg = lane & 3, gq = lane >> 2;
    const bool is_even = (tg & 1) == 0;

    const int a_row = e0 + (lane & 7) + ((lane >> 3) & 1) * 8;
    const u32 a_koff = ((lane >> 4) & 1) * 16;
    const u32 ah_base = smb + SH_HI + (u32)a_row * WROW + a_koff;
    const u32 al_base = smb + SH_LO + (u32)a_row * WROW + a_koff;
    const int b4_row = colbase + ((lane >> 4) << 3) + (lane & 7);
    const u32 b4_koff = ((lane >> 3) & 1) * 16;
    const u32 b4_base = smb + SW_HI + (u32)b4_row * WROW + b4_koff;

    float cA[6], cB[6];
    #pragma unroll
    for (int n0 = 0; n0 < 6; n0++){
        int j = cg * 12 + n0 * 2 + (tg >> 1);
        cA[n0] = g_c0[(b0 + e0 + gq) * 96 + j];
        cB[n0] = g_c0[(b0 + e0 + gq + 8) * 96 + j];
    }
    const float bex = bemb[0], bey = bemb[1];
    __syncthreads();

    for (int t = 0; t < 30; t++){
        u32 ahi[6][4], alo[6][4];
        #pragma unroll
        for (int kc = 0; kc < 6; kc++){
            ldsm4(ahi[kc][0], ahi[kc][1], ahi[kc][2], ahi[kc][3], ah_base + kc * 32);
            ldsm4(alo[kc][0], alo[kc][1], alo[kc][2], alo[kc][3], al_base + kc * 32);
        }
        __syncthreads();

        #pragma unroll
        for (int p = 0; p < 3; p++){
            float d[2][4];
            #pragma unroll
            for (int h2 = 0; h2 < 2; h2++)
                #pragma unroll
                for (int r2 = 0; r2 < 4; r2++) d[h2][r2] = 0.f;
            const u32 bp = b4_base + (u32)(p * 16) * WROW;
            #pragma unroll
            for (int kc = 0; kc < 6; kc++){
                u32 bq0, bq1, bq2, bq3;
                ldsm4(bq0, bq1, bq2, bq3, bp + kc * 32);
                mma_f16(d[0][0], d[0][1], d[0][2], d[0][3], ahi[kc], bq0, bq1);
                mma_f16(d[0][0], d[0][1], d[0][2], d[0][3], alo[kc], bq0, bq1);
                mma_f16(d[1][0], d[1][1], d[1][2], d[1][3], ahi[kc], bq2, bq3);
                mma_f16(d[1][0], d[1][1], d[1][2], d[1][3], alo[kc], bq2, bq3);
            }
            #pragma unroll
            for (int h2 = 0; h2 < 2; h2++){
                const int n0 = 2 * p + h2;
                float d0 = d[h2][0], d1 = d[h2][1], d2 = d[h2][2], d3 = d[h2][3];
                float s0 = __shfl_xor_sync(0xffffffffu, d0, 1);
                float s1 = __shfl_xor_sync(0xffffffffu, d1, 1);
                float s2 = __shfl_xor_sync(0xffffffffu, d2, 1);
                float s3 = __shfl_xor_sync(0xffffffffu, d3, 1);
                if (is_even){
                    const int r = colbase + n0 * 8 + 2 * tg;
                    const int j = r >> 2;
                    float bi = bsd[r], bf = bsd[r + 1], bg = bsd[r + 2], bo = bsd[r + 3];
                    const int eA = e0 + gq, eB = eA + 8;
                    float cnA = sigmf(d1 + bf) * cA[n0] + sigmf(d0 + bi) * tanhf_(s0 + bg);
                    float hA  = sigmf(s1 + bo) * tanhf_(cnA);
                    float cnB = sigmf(d3 + bf) * cB[n0] + sigmf(d2 + bi) * tanhf_(s2 + bg);
                    float hB  = sigmf(s3 + bo) * tanhf_(cnB);
                    cA[n0] = cnA; cB[n0] = cnB;
                    hf32[eA * HF32P + j] = hA;
                    hf32[eB * HF32P + j] = hB;
                    __half hAh = __float2half_rn(hA);
                    __half hBh = __float2half_rn(hB);
                    *(__half*)(smc + SH_HI + (eA * 104 + j) * 2) = hAh;
                    *(__half*)(smc + SH_HI + (eB * 104 + j) * 2) = hBh;
                    *(__half*)(smc + SH_LO + (eA * 104 + j) * 2) = __float2half_rn(hA - __half2float(hAh));
                    *(__half*)(smc + SH_LO + (eB * 104 + j) * 2) = __float2half_rn(hB - __half2float(hBh));
                }
            }
        }
        __syncthreads();

        if (tid < 32){
            u64 ax = 0ULL, ay = 0ULL;
            const float* hp = hf32 + tid * HF32P;
            #pragma unroll 8
            for (int kk = 0; kk < 48; kk++){
                u64 hd = *(const u64*)&hp[2 * kk];
                ffma2(ax, hd, *(const u64*)&wex[2 * kk]);
                ffma2(ay, hd, *(const u64*)&wey[2 * kk]);
            }
            float2 o; o.x = red2(ax) + bex; o.y = red2(ay) + bey;
            *(float2*)(out + (b0 + tid) * 60 + 2 * t) = o;
        }
    }
}

extern "C" void kernel_launch(void* const* d_in, const int* in_sizes, int n_in,
                              void* d_out, int out_size)
{
    (void)n_in; (void)out_size;
    const float* traj  = (const float*)d_in[0];
    const float* cent  = (const float*)d_in[1];
    const float* Wih_c = (const float*)d_in[2];
    const float* Whh_c = (const float*)d_in[3];
    const float* bih_c = (const float*)d_in[4];
    const float* bhh_c = (const float*)d_in[5];
    const float* Wih_e = (const float*)d_in[6];
    const float* Whh_e = (const float*)d_in[7];
    const float* bih_e = (const float*)d_in[8];
    const float* bhh_e = (const float*)d_in[9];
    const float* Wih_d = (const float*)d_in[10];
    const float* Whh_d = (const float*)d_in[11];
    const float* bih_d = (const float*)d_in[12];
    const float* bhh_d = (const float*)d_in[13];
    const float* W_emb = (const float*)d_in[14];
    const float* b_emb = (const float*)d_in[15];
    float* out = (float*)d_out;

    const int B = in_sizes[0] / 40;   // input_traj [B][20][2]

    // SMEM bytes: 2*G*KP*2 (W) + 2*32*KP*2 (h) + 3*G*4 (bias/wx)
    const int smc = 2*128*40*2 + 2*32*40*2 + 3*128*4;   //  27,136 (H=32, KP=40)
    const int sme = 2*256*72*2 + 2*32*72*2 + 3*256*4;   //  86,016 (H=64, KP=72)

    cudaFuncSetAttribute(lstm_rec_mma<32,100,64>, cudaFuncAttributeMaxDynamicSharedMemorySize, smc);
    cudaFuncSetAttribute(lstm_rec_mma<64, 20, 0>, cudaFuncAttributeMaxDynamicSharedMemorySize, sme);
    cudaFuncSetAttribute(lstm_dec_mma, cudaFuncAttributeMaxDynamicSharedMemorySize, SM_TOT);

    // centerline LSTM (H=32, T=100) -> g_h0/g_c0[.., 64..95]
    lstm_rec_mma<32,100,64><<<B / 32, 512, smc>>>(cent, Wih_c, Whh_c, bih_c, bhh_c);
    // encoder LSTM (H=64, T=20)    -> g_h0/g_c0[.., 0..63]
    lstm_rec_mma<64, 20, 0><<<B / 32, 512, sme>>>(traj, Wih_e, Whh_e, bih_e, bhh_e);
    // decoder on HMMA fp16 2-pass (H=96, 30 steps, 32 elems/CTA) -> out [B][30][2]
    lstm_dec_mma<<<B / 32, DNT, SM_TOT>>>(Wih_d, Whh_d, bih_d, bhh_d, W_emb, b_emb, out);
}

// round 11
// speedup vs baseline: 1.0960x; 1.0960x over previous
#include <cuda_runtime.h>
#include <cuda_fp16.h>

typedef unsigned long long u64;
typedef unsigned int u32;
#define BATCH 131072

// inter-phase state: concat layout [b][96], enc at 0..63, cent at 64..95
__device__ float g_h0[(size_t)BATCH * 96];
__device__ float g_c0[(size_t)BATCH * 96];

__device__ __forceinline__ float ex2f(float x){ float y; asm("ex2.approx.f32 %0, %1;" : "=f"(y) : "f"(x)); return y; }
__device__ __forceinline__ float rcpf(float x){ float y; asm("rcp.approx.f32 %0, %1;" : "=f"(y) : "f"(x)); return y; }
__device__ __forceinline__ float sigmf(float x){ return rcpf(1.0f + ex2f(-1.4426950408889634f * x)); }
__device__ __forceinline__ float tanhf_(float x){ return 1.0f - 2.0f * rcpf(1.0f + ex2f(2.8853900817779268f * x)); }

__device__ __forceinline__ void ffma2(u64 &d, u64 a, u64 b){
    asm("fma.rn.f32x2 %0, %1, %2, %0;" : "+l"(d) : "l"(a), "l"(b));
}
__device__ __forceinline__ float red2(u64 a){
    float lo, hi; asm("mov.b64 {%0, %1}, %2;" : "=f"(lo), "=f"(hi) : "l"(a)); return lo + hi;
}
__device__ __forceinline__ u32 smem_u32(const void* p){
    u32 a; asm("{ .reg .u64 t; cvta.to.shared.u64 t, %1; cvt.u32.u64 %0, t; }" : "=r"(a) : "l"(p)); return a;
}
__device__ __forceinline__ void ldsm4(u32 &r0, u32 &r1, u32 &r2, u32 &r3, u32 addr){
    asm volatile("ldmatrix.sync.aligned.m8n8.x4.shared.b16 {%0,%1,%2,%3}, [%4];"
        : "=r"(r0), "=r"(r1), "=r"(r2), "=r"(r3) : "r"(addr));
}
__device__ __forceinline__ void mma_f16(float &d0, float &d1, float &d2, float &d3,
                                        const u32* a, u32 b0, u32 b1){
    asm volatile("mma.sync.aligned.m16n8k16.row.col.f32.f16.f16.f32 "
        "{%0,%1,%2,%3}, {%4,%5,%6,%7}, {%8,%9}, {%0,%1,%2,%3};"
        : "+f"(d0), "+f"(d1), "+f"(d2), "+f"(d3)
        : "r"(a[0]), "r"(a[1]), "r"(a[2]), "r"(a[3]), "r"(b0), "r"(b1));
}

// ---------------------------------------------------------------------------
// cent / enc recurrent phase on HMMA, 3-pass (W split hi/lo fp16).
// NE=64 elems/CTA, 512 thr = 16 warps: rg = wid>>2 (4 x 16 elems),
// cg = wid&3 (4 x H gate-cols). W gate-interleaved: col r = 4j+g.
// x-projection (2 inputs) + bias applied in fp32 in the epilogue.
// ---------------------------------------------------------------------------
template<int H, int T, int OFF, int MINB>
__global__ __launch_bounds__(512, MINB)
void lstm_rec_mma(const float* __restrict__ x_g,
                  const float* __restrict__ Wih, const float* __restrict__ Whh,
                  const float* __restrict__ bih, const float* __restrict__ bhh)
{
    constexpr int G     = 4 * H;
    constexpr int NE    = 64;
    constexpr int KP    = H + 8;        // halves per row (16B-aligned stride)
    constexpr int WROWB = 2 * KP;       // bytes per row
    constexpr int KC    = H / 16;       // k16 chunks
    constexpr int NPAIR = H / 16;       // n8-tile pairs per warp (H cols/warp)
    constexpr int NCELL = H / 8;        // n0 cells per warp
    // SMEM byte offsets
    constexpr int SWHI = 0;
    constexpr int SWLO = SWHI + G * KP * 2;
    constexpr int SHHI = SWLO + G * KP * 2;
    constexpr int SHLO = SHHI + NE * KP * 2;
    constexpr int SBSD = SHLO + NE * KP * 2;
    constexpr int SWX0 = SBSD + G * 4;
    constexpr int SWX1 = SWX0 + G * 4;

    extern __shared__ char smc[];
    float* bsd = (float*)(smc + SBSD);
    float* wx0 = (float*)(smc + SWX0);
    float* wx1 = (float*)(smc + SWX1);
    const u32 smb = smem_u32(smc);

    const int tid = threadIdx.x;
    const size_t b0 = (size_t)blockIdx.x * NE;

    // ---- W fill: torch row = g*H+j -> interleaved col r = 4j+g, fp16 hi/lo ----
    for (int i = tid; i < G * H; i += 512){
        int trow = i / H, k = i % H;
        int g = trow / H, j = trow % H;
        float w = Whh[i];
        __half hi = __float2half_rn(w);
        __half lo = __float2half_rn(w - __half2float(hi));
        int r = 4 * j + g;
        *(__half*)(smc + SWHI + (r * KP + k) * 2) = hi;
        *(__half*)(smc + SWLO + (r * KP + k) * 2) = lo;
    }
    for (int i = tid; i < G; i += 512){
        int g = i / H, j = i % H;
        int r = 4 * j + g;
        bsd[r] = bih[i] + bhh[i];
        wx0[r] = Wih[2 * i];
        wx1[r] = Wih[2 * i + 1];
    }
    // h0 = 0
    for (int i = tid; i < NE * KP; i += 512){
        *(__half*)(smc + SHHI + i * 2) = __float2half_rn(0.f);
        *(__half*)(smc + SHLO + i * 2) = __float2half_rn(0.f);
    }

    const int wid = tid >> 5, lane = tid & 31;
    const int cg = wid & 3, rg = wid >> 2;
    const int e0 = rg * 16, colbase = cg * H;
    const int tg = lane & 3, gq = lane >> 2;
    const bool is_even = (tg & 1) == 0;

    // ldmatrix per-lane addresses
    const int a_row = e0 + (lane & 7) + ((lane >> 3) & 1) * 8;
    const u32 a_koff = ((lane >> 4) & 1) * 16;
    const u32 ah_base = smb + SHHI + (u32)a_row * WROWB + a_koff;
    const u32 al_base = smb + SHLO + (u32)a_row * WROWB + a_koff;
    const int b4_row = colbase + ((lane >> 4) << 3) + (lane & 7);
    const u32 b4_koff = ((lane >> 3) & 1) * 16;
    const u32 bh4_base = smb + SWHI + (u32)b4_row * WROWB + b4_koff;
    const u32 bl4_base = smb + SWLO + (u32)b4_row * WROWB + b4_koff;

    const int eA = e0 + gq, eB = eA + 8;
    float cA[NCELL], cB[NCELL];
    #pragma unroll
    for (int n0 = 0; n0 < NCELL; n0++){ cA[n0] = 0.f; cB[n0] = 0.f; }

    __syncthreads();

    for (int t = 0; t < T; t++){
        // x inputs for this step (even lanes consume; L1-resident after step 1)
        float2 xA = *(const float2*)(x_g + (b0 + eA) * (size_t)(2 * T) + 2 * t);
        float2 xB = *(const float2*)(x_g + (b0 + eB) * (size_t)(2 * T) + 2 * t);

        // A fragments (h hi/lo)
        u32 ahi[KC][4], alo[KC][4];
        #pragma unroll
        for (int kc = 0; kc < KC; kc++){
            ldsm4(ahi[kc][0], ahi[kc][1], ahi[kc][2], ahi[kc][3], ah_base + kc * 32);
            ldsm4(alo[kc][0], alo[kc][1], alo[kc][2], alo[kc][3], al_base + kc * 32);
        }
        __syncthreads();   // A consumed -> h SMEM writable

        #pragma unroll
        for (int p = 0; p < NPAIR; p++){
            float d[2][4];
            #pragma unroll
            for (int h2 = 0; h2 < 2; h2++)
                #pragma unroll
                for (int r2 = 0; r2 < 4; r2++) d[h2][r2] = 0.f;
            const u32 bhp = bh4_base + (u32)(p * 16) * WROWB;
            const u32 blp = bl4_base + (u32)(p * 16) * WROWB;
            #pragma unroll
            for (int kc = 0; kc < KC; kc++){
                u32 h0q, h1q, h2q, h3q, l0q, l1q, l2q, l3q;
                ldsm4(h0q, h1q, h2q, h3q, bhp + kc * 32);
                ldsm4(l0q, l1q, l2q, l3q, blp + kc * 32);
                mma_f16(d[0][0], d[0][1], d[0][2], d[0][3], ahi[kc], h0q, h1q);
                mma_f16(d[0][0], d[0][1], d[0][2], d[0][3], alo[kc], h0q, h1q);
                mma_f16(d[0][0], d[0][1], d[0][2], d[0][3], ahi[kc], l0q, l1q);
                mma_f16(d[1][0], d[1][1], d[1][2], d[1][3], ahi[kc], h2q, h3q);
                mma_f16(d[1][0], d[1][1], d[1][2], d[1][3], alo[kc], h2q, h3q);
                mma_f16(d[1][0], d[1][1], d[1][2], d[1][3], ahi[kc], l2q, l3q);
            }
            #pragma unroll
            for (int h2 = 0; h2 < 2; h2++){
                const int n0 = 2 * p + h2;
                float d0 = d[h2][0], d1 = d[h2][1], d2 = d[h2][2], d3 = d[h2][3];
                // even lanes hold (i,f); receive (g,o) from lane^1
                float s0 = __shfl_xor_sync(0xffffffffu, d0, 1);
                float s1 = __shfl_xor_sync(0xffffffffu, d1, 1);
                float s2 = __shfl_xor_sync(0xffffffffu, d2, 1);
                float s3 = __shfl_xor_sync(0xffffffffu, d3, 1);
                if (is_even){
                    const int r = colbase + n0 * 8 + 2 * tg;   // = 4j
                    const int j = r >> 2;
                    float bi = bsd[r],   wi0 = wx0[r],   wi1 = wx1[r];
                    float bf = bsd[r+1], wf0 = wx0[r+1], wf1 = wx1[r+1];
                    float bg = bsd[r+2], wg0 = wx0[r+2], wg1 = wx1[r+2];
                    float bo = bsd[r+3], wo0 = wx0[r+3], wo1 = wx1[r+3];
                    float giA = d0 + bi + xA.x * wi0 + xA.y * wi1;
                    float gfA = d1 + bf + xA.x * wf0 + xA.y * wf1;
                    float ggA = s0 + bg + xA.x * wg0 + xA.y * wg1;
                    float goA = s1 + bo + xA.x * wo0 + xA.y * wo1;
                    float cnA = sigmf(gfA) * cA[n0] + sigmf(giA) * tanhf_(ggA);
                    float hA  = sigmf(goA) * tanhf_(cnA);
                    float giB = d2 + bi + xB.x * wi0 + xB.y * wi1;
                    float gfB = d3 + bf + xB.x * wf0 + xB.y * wf1;
                    float ggB = s2 + bg + xB.x * wg0 + xB.y * wg1;
                    float goB = s3 + bo + xB.x * wo0 + xB.y * wo1;
                    float cnB = sigmf(gfB) * cB[n0] + sigmf(giB) * tanhf_(ggB);
                    float hB  = sigmf(goB) * tanhf_(cnB);
                    cA[n0] = cnA; cB[n0] = cnB;
                    __half hAh = __float2half_rn(hA);
                    __half hBh = __float2half_rn(hB);
                    *(__half*)(smc + SHHI + (eA * KP + j) * 2) = hAh;
                    *(__half*)(smc + SHHI + (eB * KP + j) * 2) = hBh;
                    *(__half*)(smc + SHLO + (eA * KP + j) * 2) = __float2half_rn(hA - __half2float(hAh));
                    *(__half*)(smc + SHLO + (eB * KP + j) * 2) = __float2half_rn(hB - __half2float(hBh));
                    if (t == T - 1){
                        g_h0[(b0 + eA) * 96 + OFF + j] = hA;
                        g_h0[(b0 + eB) * 96 + OFF + j] = hB;
                        g_c0[(b0 + eA) * 96 + OFF + j] = cnA;
                        g_c0[(b0 + eB) * 96 + OFF + j] = cnB;
                    }
                }
            }
        }
        __syncthreads();   // h ready for next step
    }
}

// ---------------------------------------------------------------------------
// decoder on HMMA, fp16 2-pass, NE=64 elems/CTA.
// 16 warps: rg = wid>>2 (4 x 16 elems), cg = wid&3 (4 x 96 gate-cols).
// ---------------------------------------------------------------------------
#define DNT 512
#define SW_HI   0          // W_hi  [384][104] fp16  (79,872)
#define SH_HI   79872      // h_hi  [64][104]  fp16  (13,312)
#define SH_LO   93184      // h_lo  [64][104]  fp16  (13,312)
#define SH_F32  106496     // h_f32 [64][100]  f32   (25,600)
#define S_BSD   132096     // bias  [384]      f32   (1,536)
#define S_WEX   133632     // [96] f32
#define S_WEY   134016     // [96] f32
#define SM_TOT  134400
#define WROW    208
#define HF32P   100

__global__ __launch_bounds__(DNT, 1)
void lstm_dec_mma(const float* __restrict__ Wih, const float* __restrict__ Whh,
                  const float* __restrict__ bih, const float* __restrict__ bhh,
                  const float* __restrict__ Wemb, const float* __restrict__ bemb,
                  float* __restrict__ out)
{
    extern __shared__ char smc[];
    float* hf32 = (float*)(smc + SH_F32);
    float* bsd  = (float*)(smc + S_BSD);
    float* wex  = (float*)(smc + S_WEX);
    float* wey  = (float*)(smc + S_WEY);
    const u32 smb = smem_u32(smc);

    const int tid = threadIdx.x;
    const size_t b0 = (size_t)blockIdx.x * 64;

    for (int i = tid; i < 384 * 96; i += DNT){
        int trow = i / 96, k = i % 96;
        int g = trow / 96, j = trow % 96;
        float w = Wih[i] + Whh[i];
        int r = 4 * j + g;
        *(__half*)(smc + SW_HI + (r * 104 + k) * 2) = __float2half_rn(w);
    }
    for (int i = tid; i < 384; i += DNT){
        int g = i / 96, j = i % 96;
        bsd[4 * j + g] = bih[i] + bhh[i];
    }
    for (int i = tid; i < 96; i += DNT){ wex[i] = Wemb[i]; wey[i] = Wemb[96 + i]; }

    for (int i = tid; i < 64 * 96; i += DNT){
        int e = i / 96, j = i % 96;
        float v = g_h0[(b0 + e) * 96 + j];
        __half hi = __float2half_rn(v);
        __half lo = __float2half_rn(v - __half2float(hi));
        hf32[e * HF32P + j] = v;
        *(__half*)(smc + SH_HI + (e * 104 + j) * 2) = hi;
        *(__half*)(smc + SH_LO + (e * 104 + j) * 2) = lo;
    }

    const int wid = tid >> 5, lane = tid & 31;
    const int cg = wid & 3, rg = wid >> 2;
    const int e0 = rg * 16, colbase = cg * 96;
    const int tg = lane & 3, gq = lane >> 2;
    const bool is_even = (tg & 1) == 0;

    const int a_row = e0 + (lane & 7) + ((lane >> 3) & 1) * 8;
    const u32 a_koff = ((lane >> 4) & 1) * 16;
    const u32 ah_base = smb + SH_HI + (u32)a_row * WROW + a_koff;
    const u32 al_base = smb + SH_LO + (u32)a_row * WROW + a_koff;
    const int b4_row = colbase + ((lane >> 4) << 3) + (lane & 7);
    const u32 b4_koff = ((lane >> 3) & 1) * 16;
    const u32 b4_base = smb + SW_HI + (u32)b4_row * WROW + b4_koff;

    float cA[12], cB[12];
    #pragma unroll
    for (int n0 = 0; n0 < 12; n0++){
        int j = cg * 24 + 2 * n0 + (tg >> 1);
        cA[n0] = g_c0[(b0 + e0 + gq) * 96 + j];
        cB[n0] = g_c0[(b0 + e0 + gq + 8) * 96 + j];
    }
    const float bex = bemb[0], bey = bemb[1];
    __syncthreads();

    for (int t = 0; t < 30; t++){
        u32 ahi[6][4], alo[6][4];
        #pragma unroll
        for (int kc = 0; kc < 6; kc++){
            ldsm4(ahi[kc][0], ahi[kc][1], ahi[kc][2], ahi[kc][3], ah_base + kc * 32);
            ldsm4(alo[kc][0], alo[kc][1], alo[kc][2], alo[kc][3], al_base + kc * 32);
        }
        __syncthreads();

        #pragma unroll
        for (int p = 0; p < 6; p++){
            float d[2][4];
            #pragma unroll
            for (int h2 = 0; h2 < 2; h2++)
                #pragma unroll
                for (int r2 = 0; r2 < 4; r2++) d[h2][r2] = 0.f;
            const u32 bp = b4_base + (u32)(p * 16) * WROW;
            #pragma unroll
            for (int kc = 0; kc < 6; kc++){
                u32 bq0, bq1, bq2, bq3;
                ldsm4(bq0, bq1, bq2, bq3, bp + kc * 32);
                mma_f16(d[0][0], d[0][1], d[0][2], d[0][3], ahi[kc], bq0, bq1);
                mma_f16(d[0][0], d[0][1], d[0][2], d[0][3], alo[kc], bq0, bq1);
                mma_f16(d[1][0], d[1][1], d[1][2], d[1][3], ahi[kc], bq2, bq3);
                mma_f16(d[1][0], d[1][1], d[1][2], d[1][3], alo[kc], bq2, bq3);
            }
            #pragma unroll
            for (int h2 = 0; h2 < 2; h2++){
                const int n0 = 2 * p + h2;
                float d0 = d[h2][0], d1 = d[h2][1], d2 = d[h2][2], d3 = d[h2][3];
                float s0 = __shfl_xor_sync(0xffffffffu, d0, 1);
                float s1 = __shfl_xor_sync(0xffffffffu, d1, 1);
                float s2 = __shfl_xor_sync(0xffffffffu, d2, 1);
                float s3 = __shfl_xor_sync(0xffffffffu, d3, 1);
                if (is_even){
                    const int r = colbase + n0 * 8 + 2 * tg;
                    const int j = r >> 2;
                    float bi = bsd[r], bf = bsd[r + 1], bg = bsd[r + 2], bo = bsd[r + 3];
                    const int eA = e0 + gq, eB = eA + 8;
                    float cnA = sigmf(d1 + bf) * cA[n0] + sigmf(d0 + bi) * tanhf_(s0 + bg);
                    float hA  = sigmf(s1 + bo) * tanhf_(cnA);
                    float cnB = sigmf(d3 + bf) * cB[n0] + sigmf(d2 + bi) * tanhf_(s2 + bg);
                    float hB  = sigmf(s3 + bo) * tanhf_(cnB);
                    cA[n0] = cnA; cB[n0] = cnB;
                    hf32[eA * HF32P + j] = hA;
                    hf32[eB * HF32P + j] = hB;
                    __half hAh = __float2half_rn(hA);
                    __half hBh = __float2half_rn(hB);
                    *(__half*)(smc + SH_HI + (eA * 104 + j) * 2) = hAh;
                    *(__half*)(smc + SH_HI + (eB * 104 + j) * 2) = hBh;
                    *(__half*)(smc + SH_LO + (eA * 104 + j) * 2) = __float2half_rn(hA - __half2float(hAh));
                    *(__half*)(smc + SH_LO + (eB * 104 + j) * 2) = __float2half_rn(hB - __half2float(hBh));
                }
            }
        }
        __syncthreads();

        if (tid < 64){
            u64 ax = 0ULL, ay = 0ULL;
            const float* hp = hf32 + tid * HF32P;
            #pragma unroll 8
            for (int kk = 0; kk < 48; kk++){
                u64 hd = *(const u64*)&hp[2 * kk];
                ffma2(ax, hd, *(const u64*)&wex[2 * kk]);
                ffma2(ay, hd, *(const u64*)&wey[2 * kk]);
            }
            float2 o; o.x = red2(ax) + bex; o.y = red2(ay) + bey;
            *(float2*)(out + (b0 + tid) * 60 + 2 * t) = o;
        }
    }
}

extern "C" void kernel_launch(void* const* d_in, const int* in_sizes, int n_in,
                              void* d_out, int out_size)
{
    (void)n_in; (void)out_size;
    const float* traj  = (const float*)d_in[0];
    const float* cent  = (const float*)d_in[1];
    const float* Wih_c = (const float*)d_in[2];
    const float* Whh_c = (const float*)d_in[3];
    const float* bih_c = (const float*)d_in[4];
    const float* bhh_c = (const float*)d_in[5];
    const float* Wih_e = (const float*)d_in[6];
    const float* Whh_e = (const float*)d_in[7];
    const float* bih_e = (const float*)d_in[8];
    const float* bhh_e = (const float*)d_in[9];
    const float* Wih_d = (const float*)d_in[10];
    const float* Whh_d = (const float*)d_in[11];
    const float* bih_d = (const float*)d_in[12];
    const float* bhh_d = (const float*)d_in[13];
    const float* W_emb = (const float*)d_in[14];
    const float* b_emb = (const float*)d_in[15];
    float* out = (float*)d_out;

    const int B = in_sizes[0] / 40;   // input_traj [B][20][2]

    // SMEM bytes: 2*G*KP*2 (W) + 2*64*KP*2 (h) + 3*G*4 (bias/wx)
    const int smc = 2*128*40*2 + 2*64*40*2 + 3*128*4;   //  32,256 (H=32, KP=40)
    const int sme = 2*256*72*2 + 2*64*72*2 + 3*256*4;   //  95,232 (H=64, KP=72)

    cudaFuncSetAttribute(lstm_rec_mma<32,100,64,2>, cudaFuncAttributeMaxDynamicSharedMemorySize, smc);
    cudaFuncSetAttribute(lstm_rec_mma<64, 20, 0,1>, cudaFuncAttributeMaxDynamicSharedMemorySize, sme);
    cudaFuncSetAttribute(lstm_dec_mma, cudaFuncAttributeMaxDynamicSharedMemorySize, SM_TOT);

    // centerline LSTM (H=32, T=100) -> g_h0/g_c0[.., 64..95]  (2 CTAs/SM)
    lstm_rec_mma<32,100,64,2><<<B / 64, 512, smc>>>(cent, Wih_c, Whh_c, bih_c, bhh_c);
    // encoder LSTM (H=64, T=20)    -> g_h0/g_c0[.., 0..63]
    lstm_rec_mma<64, 20, 0,1><<<B / 64, 512, sme>>>(traj, Wih_e, Whh_e, bih_e, bhh_e);
    // decoder on HMMA fp16 2-pass (H=96, 30 steps, 64 elems/CTA) -> out [B][30][2]
    lstm_dec_mma<<<B / 64, DNT, SM_TOT>>>(Wih_d, Whh_d, bih_d, bhh_d, W_emb, b_emb, out);
}

// round 12
// speedup vs baseline: 1.5205x; 1.3873x over previous
#include <cuda_runtime.h>
#include <cuda_fp16.h>

typedef unsigned long long u64;
typedef unsigned int u32;
#define BATCH 131072

// inter-phase state: concat layout [b][96], enc at 0..63, cent at 64..95
__device__ float g_h0[(size_t)BATCH * 96];
__device__ float g_c0[(size_t)BATCH * 96];

__device__ __forceinline__ float ex2f(float x){ float y; asm("ex2.approx.f32 %0, %1;" : "=f"(y) : "f"(x)); return y; }
__device__ __forceinline__ float rcpf(float x){ float y; asm("rcp.approx.f32 %0, %1;" : "=f"(y) : "f"(x)); return y; }
__device__ __forceinline__ float sigmf(float x){ return rcpf(1.0f + ex2f(-1.4426950408889634f * x)); }
__device__ __forceinline__ float tanhf_(float x){ return 1.0f - 2.0f * rcpf(1.0f + ex2f(2.8853900817779268f * x)); }

__device__ __forceinline__ void ffma2(u64 &d, u64 a, u64 b){
    asm("fma.rn.f32x2 %0, %1, %2, %0;" : "+l"(d) : "l"(a), "l"(b));
}
__device__ __forceinline__ float red2(u64 a){
    float lo, hi; asm("mov.b64 {%0, %1}, %2;" : "=f"(lo), "=f"(hi) : "l"(a)); return lo + hi;
}
__device__ __forceinline__ u64 pk2(float x, float y){
    u64 r; asm("mov.b64 %0, {%1, %2};" : "=l"(r) : "f"(x), "f"(y)); return r;
}
__device__ __forceinline__ u32 smem_u32(const void* p){
    u32 a; asm("{ .reg .u64 t; cvta.to.shared.u64 t, %1; cvt.u32.u64 %0, t; }" : "=r"(a) : "l"(p)); return a;
}
__device__ __forceinline__ void ldsm4(u32 &r0, u32 &r1, u32 &r2, u32 &r3, u32 addr){
    asm volatile("ldmatrix.sync.aligned.m8n8.x4.shared.b16 {%0,%1,%2,%3}, [%4];"
        : "=r"(r0), "=r"(r1), "=r"(r2), "=r"(r3) : "r"(addr));
}
__device__ __forceinline__ void mma_f16(float &d0, float &d1, float &d2, float &d3,
                                        const u32* a, u32 b0, u32 b1){
    asm volatile("mma.sync.aligned.m16n8k16.row.col.f32.f16.f16.f32 "
        "{%0,%1,%2,%3}, {%4,%5,%6,%7}, {%8,%9}, {%0,%1,%2,%3};"
        : "+f"(d0), "+f"(d1), "+f"(d2), "+f"(d3)
        : "r"(a[0]), "r"(a[1]), "r"(a[2]), "r"(a[3]), "r"(b0), "r"(b1));
}

// ---------------------------------------------------------------------------
// cent / enc recurrent phase on HMMA, 3-pass (W split hi/lo fp16).
// NE=64 elems/CTA, 16 warps: rg = wid>>2 (4 x 16 elems), cg = wid&3 (4 x H
// gate-cols). Both-lane epilogue: parity-select shfl leaves even lane with all
// 4 gates of elem eA, odd lane with elem eB — every lane updates one element.
// ---------------------------------------------------------------------------
template<int H, int T, int OFF, int MINB>
__global__ __launch_bounds__(512, MINB)
void lstm_rec_mma(const float* __restrict__ x_g,
                  const float* __restrict__ Wih, const float* __restrict__ Whh,
                  const float* __restrict__ bih, const float* __restrict__ bhh)
{
    constexpr int G     = 4 * H;
    constexpr int NE    = 64;
    constexpr int KP    = H + 8;        // halves per row (16B-aligned stride)
    constexpr int WROWB = 2 * KP;       // bytes per row
    constexpr int KC    = H / 16;       // k16 chunks
    constexpr int NPAIR = H / 16;       // n8-tile pairs per warp (H cols/warp)
    // SMEM byte offsets
    constexpr int SWHI = 0;
    constexpr int SWLO = SWHI + G * KP * 2;
    constexpr int SHHI = SWLO + G * KP * 2;
    constexpr int SHLO = SHHI + NE * KP * 2;
    constexpr int SBSD = SHLO + NE * KP * 2;
    constexpr int SWX0 = SBSD + G * 4;
    constexpr int SWX1 = SWX0 + G * 4;

    extern __shared__ char smc[];
    float* bsd = (float*)(smc + SBSD);
    float* wx0 = (float*)(smc + SWX0);
    float* wx1 = (float*)(smc + SWX1);
    const u32 smb = smem_u32(smc);

    const int tid = threadIdx.x;
    const size_t b0 = (size_t)blockIdx.x * NE;

    // ---- W fill: torch row = g*H+j -> interleaved col r = 4j+g, fp16 hi/lo ----
    for (int i = tid; i < G * H; i += 512){
        int trow = i / H, k = i % H;
        int g = trow / H, j = trow % H;
        float w = Whh[i];
        __half hi = __float2half_rn(w);
        __half lo = __float2half_rn(w - __half2float(hi));
        int r = 4 * j + g;
        *(__half*)(smc + SWHI + (r * KP + k) * 2) = hi;
        *(__half*)(smc + SWLO + (r * KP + k) * 2) = lo;
    }
    for (int i = tid; i < G; i += 512){
        int g = i / H, j = i % H;
        int r = 4 * j + g;
        bsd[r] = bih[i] + bhh[i];
        wx0[r] = Wih[2 * i];
        wx1[r] = Wih[2 * i + 1];
    }
    // h0 = 0
    for (int i = tid; i < NE * KP; i += 512){
        *(__half*)(smc + SHHI + i * 2) = __float2half_rn(0.f);
        *(__half*)(smc + SHLO + i * 2) = __float2half_rn(0.f);
    }

    const int wid = tid >> 5, lane = tid & 31;
    const int cg = wid & 3, rg = wid >> 2;
    const int e0 = rg * 16, colbase = cg * H;
    const int tg = lane & 3, gq = lane >> 2;
    const bool is_even = (tg & 1) == 0;
    const int el = e0 + gq + (is_even ? 0 : 8);   // this lane's element

    // ldmatrix per-lane addresses
    const int a_row = e0 + (lane & 7) + ((lane >> 3) & 1) * 8;
    const u32 a_koff = ((lane >> 4) & 1) * 16;
    const u32 ah_base = smb + SHHI + (u32)a_row * WROWB + a_koff;
    const u32 al_base = smb + SHLO + (u32)a_row * WROWB + a_koff;
    const int b4_row = colbase + ((lane >> 4) << 3) + (lane & 7);
    const u32 b4_koff = ((lane >> 3) & 1) * 16;
    const u32 bh4_base = smb + SWHI + (u32)b4_row * WROWB + b4_koff;
    const u32 bl4_base = smb + SWLO + (u32)b4_row * WROWB + b4_koff;

    constexpr int NCELL = H / 8;
    float c[NCELL];
    #pragma unroll
    for (int n0 = 0; n0 < NCELL; n0++) c[n0] = 0.f;

    __syncthreads();

    for (int t = 0; t < T; t++){
        // x input for this lane's element
        float2 xv = *(const float2*)(x_g + (b0 + el) * (size_t)(2 * T) + 2 * t);

        // A fragments (h hi/lo)
        u32 ahi[KC][4], alo[KC][4];
        #pragma unroll
        for (int kc = 0; kc < KC; kc++){
            ldsm4(ahi[kc][0], ahi[kc][1], ahi[kc][2], ahi[kc][3], ah_base + kc * 32);
            ldsm4(alo[kc][0], alo[kc][1], alo[kc][2], alo[kc][3], al_base + kc * 32);
        }
        __syncthreads();   // A consumed -> h SMEM writable

        #pragma unroll
        for (int p = 0; p < NPAIR; p++){
            float d[2][4];
            #pragma unroll
            for (int h2 = 0; h2 < 2; h2++)
                #pragma unroll
                for (int r2 = 0; r2 < 4; r2++) d[h2][r2] = 0.f;
            const u32 bhp = bh4_base + (u32)(p * 16) * WROWB;
            const u32 blp = bl4_base + (u32)(p * 16) * WROWB;
            #pragma unroll
            for (int kc = 0; kc < KC; kc++){
                u32 h0q, h1q, h2q, h3q, l0q, l1q, l2q, l3q;
                ldsm4(h0q, h1q, h2q, h3q, bhp + kc * 32);
                ldsm4(l0q, l1q, l2q, l3q, blp + kc * 32);
                mma_f16(d[0][0], d[0][1], d[0][2], d[0][3], ahi[kc], h0q, h1q);
                mma_f16(d[0][0], d[0][1], d[0][2], d[0][3], alo[kc], h0q, h1q);
                mma_f16(d[0][0], d[0][1], d[0][2], d[0][3], ahi[kc], l0q, l1q);
                mma_f16(d[1][0], d[1][1], d[1][2], d[1][3], ahi[kc], h2q, h3q);
                mma_f16(d[1][0], d[1][1], d[1][2], d[1][3], alo[kc], h2q, h3q);
                mma_f16(d[1][0], d[1][1], d[1][2], d[1][3], ahi[kc], l2q, l3q);
            }
            #pragma unroll
            for (int h2 = 0; h2 < 2; h2++){
                const int n0 = 2 * p + h2;
                float d0 = d[h2][0], d1 = d[h2][1], d2 = d[h2][2], d3 = d[h2][3];
                // parity-select exchange: even lane ends with eA's 4 gates,
                // odd lane with eB's 4 gates
                float ra = __shfl_xor_sync(0xffffffffu, is_even ? d2 : d0, 1);
                float rb = __shfl_xor_sync(0xffffffffu, is_even ? d3 : d1, 1);
                float gi_ = is_even ? d0 : ra;
                float gf_ = is_even ? d1 : rb;
                float gg_ = is_even ? ra : d2;
                float go_ = is_even ? rb : d3;
                const int r4 = colbase + n0 * 8 + (tg >> 1) * 4;   // = 4j
                const int j = r4 >> 2;
                float gi = gi_ + bsd[r4]   + xv.x * wx0[r4]   + xv.y * wx1[r4];
                float gf = gf_ + bsd[r4+1] + xv.x * wx0[r4+1] + xv.y * wx1[r4+1];
                float gg = gg_ + bsd[r4+2] + xv.x * wx0[r4+2] + xv.y * wx1[r4+2];
                float go = go_ + bsd[r4+3] + xv.x * wx0[r4+3] + xv.y * wx1[r4+3];
                float cn = sigmf(gf) * c[n0] + sigmf(gi) * tanhf_(gg);
                float hv = sigmf(go) * tanhf_(cn);
                c[n0] = cn;
                __half hh = __float2half_rn(hv);
                *(__half*)(smc + SHHI + (el * KP + j) * 2) = hh;
                *(__half*)(smc + SHLO + (el * KP + j) * 2) = __float2half_rn(hv - __half2float(hh));
                if (t == T - 1){
                    g_h0[(b0 + el) * 96 + OFF + j] = hv;
                    g_c0[(b0 + el) * 96 + OFF + j] = cn;
                }
            }
        }
        __syncthreads();   // h ready for next step
    }
}

// ---------------------------------------------------------------------------
// decoder on HMMA, fp16 2-pass, NE=64 elems/CTA, both-lane epilogue.
// pos output reconstructs h = hi + lo from the fp16 split (no f32 mirror).
// ---------------------------------------------------------------------------
#define DNT 512
#define SW_HI   0          // W_hi  [384][104] fp16  (79,872)
#define SH_HI   79872      // h_hi  [64][104]  fp16  (13,312)
#define SH_LO   93184      // h_lo  [64][104]  fp16  (13,312)
#define S_BSD   106496     // bias  [384]      f32   (1,536)
#define S_WEX   108032     // [96] f32
#define S_WEY   108416     // [96] f32
#define SM_TOT  108800
#define WROW    208

__global__ __launch_bounds__(DNT, 1)
void lstm_dec_mma(const float* __restrict__ Wih, const float* __restrict__ Whh,
                  const float* __restrict__ bih, const float* __restrict__ bhh,
                  const float* __restrict__ Wemb, const float* __restrict__ bemb,
                  float* __restrict__ out)
{
    extern __shared__ char smc[];
    float* bsd  = (float*)(smc + S_BSD);
    float* wex  = (float*)(smc + S_WEX);
    float* wey  = (float*)(smc + S_WEY);
    const u32 smb = smem_u32(smc);

    const int tid = threadIdx.x;
    const size_t b0 = (size_t)blockIdx.x * 64;

    for (int i = tid; i < 384 * 96; i += DNT){
        int trow = i / 96, k = i % 96;
        int g = trow / 96, j = trow % 96;
        float w = Wih[i] + Whh[i];
        int r = 4 * j + g;
        *(__half*)(smc + SW_HI + (r * 104 + k) * 2) = __float2half_rn(w);
    }
    for (int i = tid; i < 384; i += DNT){
        int g = i / 96, j = i % 96;
        bsd[4 * j + g] = bih[i] + bhh[i];
    }
    for (int i = tid; i < 96; i += DNT){ wex[i] = Wemb[i]; wey[i] = Wemb[96 + i]; }

    for (int i = tid; i < 64 * 96; i += DNT){
        int e = i / 96, j = i % 96;
        float v = g_h0[(b0 + e) * 96 + j];
        __half hi = __float2half_rn(v);
        __half lo = __float2half_rn(v - __half2float(hi));
        *(__half*)(smc + SH_HI + (e * 104 + j) * 2) = hi;
        *(__half*)(smc + SH_LO + (e * 104 + j) * 2) = lo;
    }

    const int wid = tid >> 5, lane = tid & 31;
    const int cg = wid & 3, rg = wid >> 2;
    const int e0 = rg * 16, colbase = cg * 96;
    const int tg = lane & 3, gq = lane >> 2;
    const bool is_even = (tg & 1) == 0;
    const int el = e0 + gq + (is_even ? 0 : 8);

    const int a_row = e0 + (lane & 7) + ((lane >> 3) & 1) * 8;
    const u32 a_koff = ((lane >> 4) & 1) * 16;
    const u32 ah_base = smb + SH_HI + (u32)a_row * WROW + a_koff;
    const u32 al_base = smb + SH_LO + (u32)a_row * WROW + a_koff;
    const int b4_row = colbase + ((lane >> 4) << 3) + (lane & 7);
    const u32 b4_koff = ((lane >> 3) & 1) * 16;
    const u32 b4_base = smb + SW_HI + (u32)b4_row * WROW + b4_koff;

    float c[12];
    #pragma unroll
    for (int n0 = 0; n0 < 12; n0++){
        int j = cg * 24 + 2 * n0 + (tg >> 1);
        c[n0] = g_c0[(b0 + el) * 96 + j];
    }
    const float bex = bemb[0], bey = bemb[1];
    __syncthreads();

    for (int t = 0; t < 30; t++){
        u32 ahi[6][4], alo[6][4];
        #pragma unroll
        for (int kc = 0; kc < 6; kc++){
            ldsm4(ahi[kc][0], ahi[kc][1], ahi[kc][2], ahi[kc][3], ah_base + kc * 32);
            ldsm4(alo[kc][0], alo[kc][1], alo[kc][2], alo[kc][3], al_base + kc * 32);
        }
        __syncthreads();

        #pragma unroll
        for (int p = 0; p < 6; p++){
            float d[2][4];
            #pragma unroll
            for (int h2 = 0; h2 < 2; h2++)
                #pragma unroll
                for (int r2 = 0; r2 < 4; r2++) d[h2][r2] = 0.f;
            const u32 bp = b4_base + (u32)(p * 16) * WROW;
            #pragma unroll
            for (int kc = 0; kc < 6; kc++){
                u32 bq0, bq1, bq2, bq3;
                ldsm4(bq0, bq1, bq2, bq3, bp + kc * 32);
                mma_f16(d[0][0], d[0][1], d[0][2], d[0][3], ahi[kc], bq0, bq1);
                mma_f16(d[0][0], d[0][1], d[0][2], d[0][3], alo[kc], bq0, bq1);
                mma_f16(d[1][0], d[1][1], d[1][2], d[1][3], ahi[kc], bq2, bq3);
                mma_f16(d[1][0], d[1][1], d[1][2], d[1][3], alo[kc], bq2, bq3);
            }
            #pragma unroll
            for (int h2 = 0; h2 < 2; h2++){
                const int n0 = 2 * p + h2;
                float d0 = d[h2][0], d1 = d[h2][1], d2 = d[h2][2], d3 = d[h2][3];
                float ra = __shfl_xor_sync(0xffffffffu, is_even ? d2 : d0, 1);
                float rb = __shfl_xor_sync(0xffffffffu, is_even ? d3 : d1, 1);
                float gi_ = is_even ? d0 : ra;
                float gf_ = is_even ? d1 : rb;
                float gg_ = is_even ? ra : d2;
                float go_ = is_even ? rb : d3;
                const int r4 = colbase + n0 * 8 + (tg >> 1) * 4;
                const int j = r4 >> 2;
                float cn = sigmf(gf_ + bsd[r4+1]) * c[n0] + sigmf(gi_ + bsd[r4]) * tanhf_(gg_ + bsd[r4+2]);
                float hv = sigmf(go_ + bsd[r4+3]) * tanhf_(cn);
                c[n0] = cn;
                __half hh = __float2half_rn(hv);
                *(__half*)(smc + SH_HI + (el * 104 + j) * 2) = hh;
                *(__half*)(smc + SH_LO + (el * 104 + j) * 2) = __float2half_rn(hv - __half2float(hh));
            }
        }
        __syncthreads();

        // pos output: 64 threads, one elem each; h = hi + lo (exact split)
        if (tid < 64){
            u64 ax = 0ULL, ay = 0ULL;
            const __half2* ph = (const __half2*)(smc + SH_HI + tid * WROW);
            const __half2* pl = (const __half2*)(smc + SH_LO + tid * WROW);
            #pragma unroll 8
            for (int kk = 0; kk < 48; kk++){
                float2 hi = __half22float2(ph[kk]);
                float2 lo = __half22float2(pl[kk]);
                u64 hd = pk2(hi.x + lo.x, hi.y + lo.y);
                ffma2(ax, hd, *(const u64*)&wex[2 * kk]);
                ffma2(ay, hd, *(const u64*)&wey[2 * kk]);
            }
            float2 o; o.x = red2(ax) + bex; o.y = red2(ay) + bey;
            *(float2*)(out + (b0 + tid) * 60 + 2 * t) = o;
        }
    }
}

extern "C" void kernel_launch(void* const* d_in, const int* in_sizes, int n_in,
                              void* d_out, int out_size)
{
    (void)n_in; (void)out_size;
    const float* traj  = (const float*)d_in[0];
    const float* cent  = (const float*)d_in[1];
    const float* Wih_c = (const float*)d_in[2];
    const float* Whh_c = (const float*)d_in[3];
    const float* bih_c = (const float*)d_in[4];
    const float* bhh_c = (const float*)d_in[5];
    const float* Wih_e = (const float*)d_in[6];
    const float* Whh_e = (const float*)d_in[7];
    const float* bih_e = (const float*)d_in[8];
    const float* bhh_e = (const float*)d_in[9];
    const float* Wih_d = (const float*)d_in[10];
    const float* Whh_d = (const float*)d_in[11];
    const float* bih_d = (const float*)d_in[12];
    const float* bhh_d = (const float*)d_in[13];
    const float* W_emb = (const float*)d_in[14];
    const float* b_emb = (const float*)d_in[15];
    float* out = (float*)d_out;

    const int B = in_sizes[0] / 40;   // input_traj [B][20][2]

    // SMEM bytes: 2*G*KP*2 (W) + 2*64*KP*2 (h) + 3*G*4 (bias/wx)
    const int smc = 2*128*40*2 + 2*64*40*2 + 3*128*4;   //  32,256 (H=32, KP=40)
    const int sme = 2*256*72*2 + 2*64*72*2 + 3*256*4;   //  95,232 (H=64, KP=72)

    cudaFuncSetAttribute(lstm_rec_mma<32,100,64,2>, cudaFuncAttributeMaxDynamicSharedMemorySize, smc);
    cudaFuncSetAttribute(lstm_rec_mma<64, 20, 0,1>, cudaFuncAttributeMaxDynamicSharedMemorySize, sme);
    cudaFuncSetAttribute(lstm_dec_mma, cudaFuncAttributeMaxDynamicSharedMemorySize, SM_TOT);

    // centerline LSTM (H=32, T=100) -> g_h0/g_c0[.., 64..95]  (2 CTAs/SM)
    lstm_rec_mma<32,100,64,2><<<B / 64, 512, smc>>>(cent, Wih_c, Whh_c, bih_c, bhh_c);
    // encoder LSTM (H=64, T=20)    -> g_h0/g_c0[.., 0..63]
    lstm_rec_mma<64, 20, 0,1><<<B / 64, 512, sme>>>(traj, Wih_e, Whh_e, bih_e, bhh_e);
    // decoder on HMMA fp16 2-pass (H=96, 30 steps, 64 elems/CTA) -> out [B][30][2]
    lstm_dec_mma<<<B / 64, DNT, SM_TOT>>>(Wih_d, Whh_d, bih_d, bhh_d, W_emb, b_emb, out);
}

// round 13
// speedup vs baseline: 1.5435x; 1.0151x over previous
#include <cuda_runtime.h>
#include <cuda_fp16.h>

typedef unsigned long long u64;
typedef unsigned int u32;
#define BATCH 131072

// inter-phase state: concat layout [b][96], enc at 0..63, cent at 64..95
__device__ float g_h0[(size_t)BATCH * 96];
__device__ float g_c0[(size_t)BATCH * 96];

__device__ __forceinline__ float ex2f(float x){ float y; asm("ex2.approx.f32 %0, %1;" : "=f"(y) : "f"(x)); return y; }
__device__ __forceinline__ float rcpf(float x){ float y; asm("rcp.approx.f32 %0, %1;" : "=f"(y) : "f"(x)); return y; }
__device__ __forceinline__ float sigmf(float x){ return rcpf(1.0f + ex2f(-1.4426950408889634f * x)); }
__device__ __forceinline__ float tanhf_(float x){ return 1.0f - 2.0f * rcpf(1.0f + ex2f(2.8853900817779268f * x)); }

__device__ __forceinline__ void ffma2(u64 &d, u64 a, u64 b){
    asm("fma.rn.f32x2 %0, %1, %2, %0;" : "+l"(d) : "l"(a), "l"(b));
}
__device__ __forceinline__ float red2(u64 a){
    float lo, hi; asm("mov.b64 {%0, %1}, %2;" : "=f"(lo), "=f"(hi) : "l"(a)); return lo + hi;
}
__device__ __forceinline__ u64 pk2(float x, float y){
    u64 r; asm("mov.b64 %0, {%1, %2};" : "=l"(r) : "f"(x), "f"(y)); return r;
}
__device__ __forceinline__ u32 smem_u32(const void* p){
    u32 a; asm("{ .reg .u64 t; cvta.to.shared.u64 t, %1; cvt.u32.u64 %0, t; }" : "=r"(a) : "l"(p)); return a;
}
__device__ __forceinline__ void ldsm4(u32 &r0, u32 &r1, u32 &r2, u32 &r3, u32 addr){
    asm volatile("ldmatrix.sync.aligned.m8n8.x4.shared.b16 {%0,%1,%2,%3}, [%4];"
        : "=r"(r0), "=r"(r1), "=r"(r2), "=r"(r3) : "r"(addr));
}
__device__ __forceinline__ void mma_f16(float &d0, float &d1, float &d2, float &d3,
                                        const u32* a, u32 b0, u32 b1){
    asm volatile("mma.sync.aligned.m16n8k16.row.col.f32.f16.f16.f32 "
        "{%0,%1,%2,%3}, {%4,%5,%6,%7}, {%8,%9}, {%0,%1,%2,%3};"
        : "+f"(d0), "+f"(d1), "+f"(d2), "+f"(d3)
        : "r"(a[0]), "r"(a[1]), "r"(a[2]), "r"(a[3]), "r"(b0), "r"(b1));
}

// ---------------------------------------------------------------------------
// cent / enc recurrent phase on HMMA, 3-pass (W split hi/lo fp16).
// NE=64 elems/CTA, 16 warps: rg = wid>>2 (4 x 16 elems), cg = wid&3 (4 x H
// gate-cols). Both-lane epilogue. Double-buffered h: step t reads buf[t&1],
// writes buf[(t+1)&1] -> ONE barrier per step.
// ---------------------------------------------------------------------------
template<int H, int T, int OFF, int MINB>
__global__ __launch_bounds__(512, MINB)
void lstm_rec_mma(const float* __restrict__ x_g,
                  const float* __restrict__ Wih, const float* __restrict__ Whh,
                  const float* __restrict__ bih, const float* __restrict__ bhh)
{
    constexpr int G     = 4 * H;
    constexpr int NE    = 64;
    constexpr int KP    = H + 8;        // halves per row (16B-aligned stride)
    constexpr int WROWB = 2 * KP;       // bytes per row
    constexpr int KC    = H / 16;       // k16 chunks
    constexpr int NPAIR = H / 16;       // n8-tile pairs per warp (H cols/warp)
    constexpr int HBUF  = NE * WROWB;   // one h buffer, bytes
    // SMEM byte offsets
    constexpr int SWHI = 0;
    constexpr int SWLO = SWHI + G * KP * 2;
    constexpr int SHHI = SWLO + G * KP * 2;   // 2 buffers
    constexpr int SHLO = SHHI + 2 * HBUF;     // 2 buffers
    constexpr int SBSD = SHLO + 2 * HBUF;
    constexpr int SWX0 = SBSD + G * 4;
    constexpr int SWX1 = SWX0 + G * 4;

    extern __shared__ char smc[];
    float* bsd = (float*)(smc + SBSD);
    float* wx0 = (float*)(smc + SWX0);
    float* wx1 = (float*)(smc + SWX1);
    const u32 smb = smem_u32(smc);

    const int tid = threadIdx.x;
    const size_t b0 = (size_t)blockIdx.x * NE;

    // ---- W fill: torch row = g*H+j -> interleaved col r = 4j+g, fp16 hi/lo ----
    for (int i = tid; i < G * H; i += 512){
        int trow = i / H, k = i % H;
        int g = trow / H, j = trow % H;
        float w = Whh[i];
        __half hi = __float2half_rn(w);
        __half lo = __float2half_rn(w - __half2float(hi));
        int r = 4 * j + g;
        *(__half*)(smc + SWHI + (r * KP + k) * 2) = hi;
        *(__half*)(smc + SWLO + (r * KP + k) * 2) = lo;
    }
    for (int i = tid; i < G; i += 512){
        int g = i / H, j = i % H;
        int r = 4 * j + g;
        bsd[r] = bih[i] + bhh[i];
        wx0[r] = Wih[2 * i];
        wx1[r] = Wih[2 * i + 1];
    }
    // h0 = 0 into buffer 0
    for (int i = tid; i < NE * KP; i += 512){
        *(__half*)(smc + SHHI + i * 2) = __float2half_rn(0.f);
        *(__half*)(smc + SHLO + i * 2) = __float2half_rn(0.f);
    }

    const int wid = tid >> 5, lane = tid & 31;
    const int cg = wid & 3, rg = wid >> 2;
    const int e0 = rg * 16, colbase = cg * H;
    const int tg = lane & 3, gq = lane >> 2;
    const bool is_even = (tg & 1) == 0;
    const int el = e0 + gq + (is_even ? 0 : 8);   // this lane's element

    // ldmatrix per-lane addresses (buffer 0 bases)
    const int a_row = e0 + (lane & 7) + ((lane >> 3) & 1) * 8;
    const u32 a_koff = ((lane >> 4) & 1) * 16;
    const u32 ah_base = smb + SHHI + (u32)a_row * WROWB + a_koff;
    const u32 al_base = smb + SHLO + (u32)a_row * WROWB + a_koff;
    const int b4_row = colbase + ((lane >> 4) << 3) + (lane & 7);
    const u32 b4_koff = ((lane >> 3) & 1) * 16;
    const u32 bh4_base = smb + SWHI + (u32)b4_row * WROWB + b4_koff;
    const u32 bl4_base = smb + SWLO + (u32)b4_row * WROWB + b4_koff;

    constexpr int NCELL = H / 8;
    float c[NCELL];
    #pragma unroll
    for (int n0 = 0; n0 < NCELL; n0++) c[n0] = 0.f;

    __syncthreads();

    for (int t = 0; t < T; t++){
        const u32 roff = (u32)(t & 1) * HBUF;        // read buffer
        const u32 woff = (u32)((t + 1) & 1) * HBUF;  // write buffer

        // x input for this lane's element
        float2 xv = *(const float2*)(x_g + (b0 + el) * (size_t)(2 * T) + 2 * t);

        // A fragments (h hi/lo) from read buffer
        u32 ahi[KC][4], alo[KC][4];
        #pragma unroll
        for (int kc = 0; kc < KC; kc++){
            ldsm4(ahi[kc][0], ahi[kc][1], ahi[kc][2], ahi[kc][3], ah_base + roff + kc * 32);
            ldsm4(alo[kc][0], alo[kc][1], alo[kc][2], alo[kc][3], al_base + roff + kc * 32);
        }

        #pragma unroll
        for (int p = 0; p < NPAIR; p++){
            float d[2][4];
            #pragma unroll
            for (int h2 = 0; h2 < 2; h2++)
                #pragma unroll
                for (int r2 = 0; r2 < 4; r2++) d[h2][r2] = 0.f;
            const u32 bhp = bh4_base + (u32)(p * 16) * WROWB;
            const u32 blp = bl4_base + (u32)(p * 16) * WROWB;
            #pragma unroll
            for (int kc = 0; kc < KC; kc++){
                u32 h0q, h1q, h2q, h3q, l0q, l1q, l2q, l3q;
                ldsm4(h0q, h1q, h2q, h3q, bhp + kc * 32);
                ldsm4(l0q, l1q, l2q, l3q, blp + kc * 32);
                mma_f16(d[0][0], d[0][1], d[0][2], d[0][3], ahi[kc], h0q, h1q);
                mma_f16(d[0][0], d[0][1], d[0][2], d[0][3], alo[kc], h0q, h1q);
                mma_f16(d[0][0], d[0][1], d[0][2], d[0][3], ahi[kc], l0q, l1q);
                mma_f16(d[1][0], d[1][1], d[1][2], d[1][3], ahi[kc], h2q, h3q);
                mma_f16(d[1][0], d[1][1], d[1][2], d[1][3], alo[kc], h2q, h3q);
                mma_f16(d[1][0], d[1][1], d[1][2], d[1][3], ahi[kc], l2q, l3q);
            }
            #pragma unroll
            for (int h2 = 0; h2 < 2; h2++){
                const int n0 = 2 * p + h2;
                float d0 = d[h2][0], d1 = d[h2][1], d2 = d[h2][2], d3 = d[h2][3];
                // parity-select exchange: even lane -> eA's 4 gates, odd -> eB's
                float ra = __shfl_xor_sync(0xffffffffu, is_even ? d2 : d0, 1);
                float rb = __shfl_xor_sync(0xffffffffu, is_even ? d3 : d1, 1);
                float gi_ = is_even ? d0 : ra;
                float gf_ = is_even ? d1 : rb;
                float gg_ = is_even ? ra : d2;
                float go_ = is_even ? rb : d3;
                const int r4 = colbase + n0 * 8 + (tg >> 1) * 4;   // = 4j
                const int j = r4 >> 2;
                float gi = gi_ + bsd[r4]   + xv.x * wx0[r4]   + xv.y * wx1[r4];
                float gf = gf_ + bsd[r4+1] + xv.x * wx0[r4+1] + xv.y * wx1[r4+1];
                float gg = gg_ + bsd[r4+2] + xv.x * wx0[r4+2] + xv.y * wx1[r4+2];
                float go = go_ + bsd[r4+3] + xv.x * wx0[r4+3] + xv.y * wx1[r4+3];
                float cn = sigmf(gf) * c[n0] + sigmf(gi) * tanhf_(gg);
                float hv = sigmf(go) * tanhf_(cn);
                c[n0] = cn;
                __half hh = __float2half_rn(hv);
                *(__half*)(smc + SHHI + woff + (el * KP + j) * 2) = hh;
                *(__half*)(smc + SHLO + woff + (el * KP + j) * 2) = __float2half_rn(hv - __half2float(hh));
                if (t == T - 1){
                    g_h0[(b0 + el) * 96 + OFF + j] = hv;
                    g_c0[(b0 + el) * 96 + OFF + j] = cn;
                }
            }
        }
        __syncthreads();   // single barrier: h_{t+1} visible, step t reads done
    }
}

// ---------------------------------------------------------------------------
// decoder on HMMA, fp16 2-pass, NE=64 elems/CTA, both-lane epilogue,
// double-buffered h (one barrier per step).
// ---------------------------------------------------------------------------
#define DNT 512
#define SW_HI   0          // W_hi  [384][104] fp16          (79,872)
#define SH_HI   79872      // h_hi  2 x [64][104] fp16       (26,624)
#define SH_LO   106496     // h_lo  2 x [64][104] fp16       (26,624)
#define S_BSD   133120     // bias  [384] f32                (1,536)
#define S_WEX   134656     // [96] f32
#define S_WEY   135040     // [96] f32
#define SM_TOT  135424
#define WROW    208
#define DHBUF   (64 * WROW)   // 13,312 bytes per h buffer

__global__ __launch_bounds__(DNT, 1)
void lstm_dec_mma(const float* __restrict__ Wih, const float* __restrict__ Whh,
                  const float* __restrict__ bih, const float* __restrict__ bhh,
                  const float* __restrict__ Wemb, const float* __restrict__ bemb,
                  float* __restrict__ out)
{
    extern __shared__ char smc[];
    float* bsd  = (float*)(smc + S_BSD);
    float* wex  = (float*)(smc + S_WEX);
    float* wey  = (float*)(smc + S_WEY);
    const u32 smb = smem_u32(smc);

    const int tid = threadIdx.x;
    const size_t b0 = (size_t)blockIdx.x * 64;

    for (int i = tid; i < 384 * 96; i += DNT){
        int trow = i / 96, k = i % 96;
        int g = trow / 96, j = trow % 96;
        float w = Wih[i] + Whh[i];
        int r = 4 * j + g;
        *(__half*)(smc + SW_HI + (r * 104 + k) * 2) = __float2half_rn(w);
    }
    for (int i = tid; i < 384; i += DNT){
        int g = i / 96, j = i % 96;
        bsd[4 * j + g] = bih[i] + bhh[i];
    }
    for (int i = tid; i < 96; i += DNT){ wex[i] = Wemb[i]; wey[i] = Wemb[96 + i]; }

    // h0 into buffer 0
    for (int i = tid; i < 64 * 96; i += DNT){
        int e = i / 96, j = i % 96;
        float v = g_h0[(b0 + e) * 96 + j];
        __half hi = __float2half_rn(v);
        __half lo = __float2half_rn(v - __half2float(hi));
        *(__half*)(smc + SH_HI + (e * 104 + j) * 2) = hi;
        *(__half*)(smc + SH_LO + (e * 104 + j) * 2) = lo;
    }

    const int wid = tid >> 5, lane = tid & 31;
    const int cg = wid & 3, rg = wid >> 2;
    const int e0 = rg * 16, colbase = cg * 96;
    const int tg = lane & 3, gq = lane >> 2;
    const bool is_even = (tg & 1) == 0;
    const int el = e0 + gq + (is_even ? 0 : 8);

    const int a_row = e0 + (lane & 7) + ((lane >> 3) & 1) * 8;
    const u32 a_koff = ((lane >> 4) & 1) * 16;
    const u32 ah_base = smb + SH_HI + (u32)a_row * WROW + a_koff;
    const u32 al_base = smb + SH_LO + (u32)a_row * WROW + a_koff;
    const int b4_row = colbase + ((lane >> 4) << 3) + (lane & 7);
    const u32 b4_koff = ((lane >> 3) & 1) * 16;
    const u32 b4_base = smb + SW_HI + (u32)b4_row * WROW + b4_koff;

    float c[12];
    #pragma unroll
    for (int n0 = 0; n0 < 12; n0++){
        int j = cg * 24 + 2 * n0 + (tg >> 1);
        c[n0] = g_c0[(b0 + el) * 96 + j];
    }
    const float bex = bemb[0], bey = bemb[1];
    __syncthreads();

    for (int t = 0; t < 30; t++){
        const u32 roff = (u32)(t & 1) * DHBUF;
        const u32 woff = (u32)((t + 1) & 1) * DHBUF;

        u32 ahi[6][4], alo[6][4];
        #pragma unroll
        for (int kc = 0; kc < 6; kc++){
            ldsm4(ahi[kc][0], ahi[kc][1], ahi[kc][2], ahi[kc][3], ah_base + roff + kc * 32);
            ldsm4(alo[kc][0], alo[kc][1], alo[kc][2], alo[kc][3], al_base + roff + kc * 32);
        }

        #pragma unroll
        for (int p = 0; p < 6; p++){
            float d[2][4];
            #pragma unroll
            for (int h2 = 0; h2 < 2; h2++)
                #pragma unroll
                for (int r2 = 0; r2 < 4; r2++) d[h2][r2] = 0.f;
            const u32 bp = b4_base + (u32)(p * 16) * WROW;
            #pragma unroll
            for (int kc = 0; kc < 6; kc++){
                u32 bq0, bq1, bq2, bq3;
                ldsm4(bq0, bq1, bq2, bq3, bp + kc * 32);
                mma_f16(d[0][0], d[0][1], d[0][2], d[0][3], ahi[kc], bq0, bq1);
                mma_f16(d[0][0], d[0][1], d[0][2], d[0][3], alo[kc], bq0, bq1);
                mma_f16(d[1][0], d[1][1], d[1][2], d[1][3], ahi[kc], bq2, bq3);
                mma_f16(d[1][0], d[1][1], d[1][2], d[1][3], alo[kc], bq2, bq3);
            }
            #pragma unroll
            for (int h2 = 0; h2 < 2; h2++){
                const int n0 = 2 * p + h2;
                float d0 = d[h2][0], d1 = d[h2][1], d2 = d[h2][2], d3 = d[h2][3];
                float ra = __shfl_xor_sync(0xffffffffu, is_even ? d2 : d0, 1);
                float rb = __shfl_xor_sync(0xffffffffu, is_even ? d3 : d1, 1);
                float gi_ = is_even ? d0 : ra;
                float gf_ = is_even ? d1 : rb;
                float gg_ = is_even ? ra : d2;
                float go_ = is_even ? rb : d3;
                const int r4 = colbase + n0 * 8 + (tg >> 1) * 4;
                const int j = r4 >> 2;
                float cn = sigmf(gf_ + bsd[r4+1]) * c[n0] + sigmf(gi_ + bsd[r4]) * tanhf_(gg_ + bsd[r4+2]);
                float hv = sigmf(go_ + bsd[r4+3]) * tanhf_(cn);
                c[n0] = cn;
                __half hh = __float2half_rn(hv);
                *(__half*)(smc + SH_HI + woff + (el * 104 + j) * 2) = hh;
                *(__half*)(smc + SH_LO + woff + (el * 104 + j) * 2) = __float2half_rn(hv - __half2float(hh));
            }
        }
        __syncthreads();   // single barrier: h_t visible for pos + next step

        // pos output: 64 threads, one elem each; h = hi + lo (exact split).
        // Reads write-buffer (h_t); next step writes the OTHER buffer -> safe.
        if (tid < 64){
            u64 ax = 0ULL, ay = 0ULL;
            const __half2* ph = (const __half2*)(smc + SH_HI + woff + tid * WROW);
            const __half2* pl = (const __half2*)(smc + SH_LO + woff + tid * WROW);
            #pragma unroll 8
            for (int kk = 0; kk < 48; kk++){
                float2 hi = __half22float2(ph[kk]);
                float2 lo = __half22float2(pl[kk]);
                u64 hd = pk2(hi.x + lo.x, hi.y + lo.y);
                ffma2(ax, hd, *(const u64*)&wex[2 * kk]);
                ffma2(ay, hd, *(const u64*)&wey[2 * kk]);
            }
            float2 o; o.x = red2(ax) + bex; o.y = red2(ay) + bey;
            *(float2*)(out + (b0 + tid) * 60 + 2 * t) = o;
        }
    }
}

extern "C" void kernel_launch(void* const* d_in, const int* in_sizes, int n_in,
                              void* d_out, int out_size)
{
    (void)n_in; (void)out_size;
    const float* traj  = (const float*)d_in[0];
    const float* cent  = (const float*)d_in[1];
    const float* Wih_c = (const float*)d_in[2];
    const float* Whh_c = (const float*)d_in[3];
    const float* bih_c = (const float*)d_in[4];
    const float* bhh_c = (const float*)d_in[5];
    const float* Wih_e = (const float*)d_in[6];
    const float* Whh_e = (const float*)d_in[7];
    const float* bih_e = (const float*)d_in[8];
    const float* bhh_e = (const float*)d_in[9];
    const float* Wih_d = (const float*)d_in[10];
    const float* Whh_d = (const float*)d_in[11];
    const float* bih_d = (const float*)d_in[12];
    const float* bhh_d = (const float*)d_in[13];
    const float* W_emb = (const float*)d_in[14];
    const float* b_emb = (const float*)d_in[15];
    float* out = (float*)d_out;

    const int B = in_sizes[0] / 40;   // input_traj [B][20][2]

    // SMEM bytes: 2*G*KP*2 (W hi/lo) + 4*64*KP*2 (h hi/lo x 2 buf) + 3*G*4
    const int smc = 2*128*40*2 + 4*64*40*2 + 3*128*4;   //  42,496 (H=32, KP=40)
    const int sme = 2*256*72*2 + 4*64*72*2 + 3*256*4;   // 113,664 (H=64, KP=72)

    cudaFuncSetAttribute(lstm_rec_mma<32,100,64,2>, cudaFuncAttributeMaxDynamicSharedMemorySize, smc);
    cudaFuncSetAttribute(lstm_rec_mma<64, 20, 0,1>, cudaFuncAttributeMaxDynamicSharedMemorySize, sme);
    cudaFuncSetAttribute(lstm_dec_mma, cudaFuncAttributeMaxDynamicSharedMemorySize, SM_TOT);

    // centerline LSTM (H=32, T=100) -> g_h0/g_c0[.., 64..95]  (2 CTAs/SM)
    lstm_rec_mma<32,100,64,2><<<B / 64, 512, smc>>>(cent, Wih_c, Whh_c, bih_c, bhh_c);
    // encoder LSTM (H=64, T=20)    -> g_h0/g_c0[.., 0..63]
    lstm_rec_mma<64, 20, 0,1><<<B / 64, 512, sme>>>(traj, Wih_e, Whh_e, bih_e, bhh_e);
    // decoder on HMMA fp16 2-pass (H=96, 30 steps, 64 elems/CTA) -> out [B][30][2]
    lstm_dec_mma<<<B / 64, DNT, SM_TOT>>>(Wih_d, Whh_d, bih_d, bhh_d, W_emb, b_emb, out);
}